// round 6
// baseline (speedup 1.0000x reference)
#include <cuda_runtime.h>
#include <cuda_bf16.h>
#include <stdint.h>
#include <math.h>

#define BATCH 4
#define SEQ   2048
#define DIM   1024
#define MTOT  (BATCH * SEQ)   // 8192
#define SCALE 0.03125f        // 1/sqrt(1024)

// ---------------------------------------------------------------------------
// Device-global scratch (allocation-guard safe)
// ---------------------------------------------------------------------------
__device__ float g_V[(size_t)MTOT * DIM];                    // V fp32 (pre-transpose)
__device__ float g_S[(size_t)BATCH * SEQ * SEQ];             // raw scores
__device__ __nv_bfloat16 g_Xh[(size_t)MTOT * DIM];           // x split [m][k]
__device__ __nv_bfloat16 g_Xl[(size_t)MTOT * DIM];
__device__ __nv_bfloat16 g_Qh[(size_t)MTOT * DIM];           // Q split [m][d]
__device__ __nv_bfloat16 g_Ql[(size_t)MTOT * DIM];
__device__ __nv_bfloat16 g_Kh[(size_t)MTOT * DIM];           // K split [m][d]
__device__ __nv_bfloat16 g_Kl[(size_t)MTOT * DIM];
__device__ __nv_bfloat16 g_Ph[(size_t)BATCH * SEQ * SEQ];    // softmax P split [q][s]
__device__ __nv_bfloat16 g_Pl[(size_t)BATCH * SEQ * SEQ];
__device__ __nv_bfloat16 g_WT_hi[(size_t)3 * DIM * DIM];     // W^T split [w][n][k]
__device__ __nv_bfloat16 g_WT_lo[(size_t)3 * DIM * DIM];
__device__ __nv_bfloat16 g_VT_hi[(size_t)BATCH * DIM * SEQ]; // V^T split [b][d][s]
__device__ __nv_bfloat16 g_VT_lo[(size_t)BATCH * DIM * SEQ];

// 64B-row swizzle: XOR row bits[1:3) into 16B-chunk bits[4:6)
#define SWZ32(o) ((o) ^ (((o) >> 3) & 0x30))
#define TILE_BYTES 8192         // 128 rows x 32 cols bf16
#define STAGE_BYTES 32768       // ahi @0, alo @8K, bhi @16K, blo @24K
#define NSTAGE 3

__device__ __forceinline__ uint32_t su32(const void* p) {
    uint32_t a;
    asm("{ .reg .u64 t; cvta.to.shared.u64 t, %1; cvt.u32.u64 %0, t; }"
        : "=r"(a) : "l"(p));
    return a;
}

__device__ __forceinline__ void ldsm4(uint32_t* r, uint32_t addr) {
    asm volatile("ldmatrix.sync.aligned.m8n8.x4.shared.b16 {%0,%1,%2,%3}, [%4];"
                 : "=r"(r[0]), "=r"(r[1]), "=r"(r[2]), "=r"(r[3]) : "r"(addr));
}

__device__ __forceinline__ void mma16816(float* d, const uint32_t* a,
                                         uint32_t b0, uint32_t b1) {
    asm volatile(
        "mma.sync.aligned.m16n8k16.row.col.f32.bf16.bf16.f32 "
        "{%0,%1,%2,%3}, {%4,%5,%6,%7}, {%8,%9}, {%0,%1,%2,%3};"
        : "+f"(d[0]), "+f"(d[1]), "+f"(d[2]), "+f"(d[3])
        : "r"(a[0]), "r"(a[1]), "r"(a[2]), "r"(a[3]), "r"(b0), "r"(b1));
}

__device__ __forceinline__ void cp_commit() {
    asm volatile("cp.async.commit_group;" ::: "memory");
}
__device__ __forceinline__ void cp_wait2() {
    asm volatile("cp.async.wait_group 2;" ::: "memory");
}
__device__ __forceinline__ void cp_wait1() {
    asm volatile("cp.async.wait_group 1;" ::: "memory");
}
__device__ __forceinline__ void cp_wait0() {
    asm volatile("cp.async.wait_group 0;" ::: "memory");
}

// Async load of one 128x32 bf16 tile (64B rows, SWZ32) into SMEM
__device__ __forceinline__ void async_tile(uint32_t dst, const __nv_bfloat16* src,
                                           int ld, int tid) {
    #pragma unroll
    for (int t = 0; t < 2; t++) {
        const int idx = tid + t * 256;      // 0..511
        const int row = idx >> 2;
        const int c = idx & 3;              // 16B chunk in 64B row
        const uint32_t d = dst + SWZ32((uint32_t)(row * 64 + c * 16));
        asm volatile("cp.async.cg.shared.global [%0], [%1], 16;"
                     :: "r"(d), "l"(src + (size_t)row * ld + c * 8));
    }
}

__device__ __forceinline__ void load_chunk(uint32_t stage_base,
                                           const __nv_bfloat16* Ah,
                                           const __nv_bfloat16* Al, int lda,
                                           const __nv_bfloat16* Bh,
                                           const __nv_bfloat16* Bl, int ldb,
                                           int kc, int tid) {
    async_tile(stage_base,         Ah + kc * 32, lda, tid);
    async_tile(stage_base + 8192,  Al + kc * 32, lda, tid);
    async_tile(stage_base + 16384, Bh + kc * 32, ldb, tid);
    async_tile(stage_base + 24576, Bl + kc * 32, ldb, tid);
    cp_commit();
}

// ---------------------------------------------------------------------------
// Warp-level K-chunk compute: 2 k16 steps, bf16x3, term-major MMA order
// warp grid: wm in [0,4) -> 32 rows, wn in [0,2) -> 64 cols
// ---------------------------------------------------------------------------
__device__ __forceinline__ void compute_chunk(uint32_t stage_base,
                                              float acc[2][8][4], int lane,
                                              int wm, int wn) {
    const uint32_t ahi_b = stage_base;
    const uint32_t alo_b = stage_base + 8192;
    const uint32_t bhi_b = stage_base + 16384;
    const uint32_t blo_b = stage_base + 24576;
    const int ar = lane & 15;
    const int ac = (lane >> 4) * 16;
    const int br = ((lane >> 4) & 1) * 8 + (lane & 7);
    const int bc = ((lane >> 3) & 1) * 16;
    #pragma unroll
    for (int ks = 0; ks < 2; ks++) {
        uint32_t AH[2][4], AL[2][4], BH[4][4], BL[4][4];
        #pragma unroll
        for (int mt = 0; mt < 2; mt++) {
            const uint32_t off =
                SWZ32((uint32_t)((wm * 32 + mt * 16 + ar) * 64 + ks * 32 + ac));
            ldsm4(AH[mt], ahi_b + off);
            ldsm4(AL[mt], alo_b + off);
        }
        #pragma unroll
        for (int p = 0; p < 4; p++) {
            const uint32_t off =
                SWZ32((uint32_t)((wn * 64 + p * 16 + br) * 64 + ks * 32 + bc));
            ldsm4(BH[p], bhi_b + off);
            ldsm4(BL[p], blo_b + off);
        }
        // term-major: consecutive MMAs always hit different accumulators
        #pragma unroll
        for (int mt = 0; mt < 2; mt++)
            #pragma unroll
            for (int nt = 0; nt < 8; nt++) {
                const int p = nt >> 1, h = (nt & 1) * 2;
                mma16816(acc[mt][nt], AH[mt], BH[p][h], BH[p][h + 1]);
            }
        #pragma unroll
        for (int mt = 0; mt < 2; mt++)
            #pragma unroll
            for (int nt = 0; nt < 8; nt++) {
                const int p = nt >> 1, h = (nt & 1) * 2;
                mma16816(acc[mt][nt], AH[mt], BL[p][h], BL[p][h + 1]);
            }
        #pragma unroll
        for (int mt = 0; mt < 2; mt++)
            #pragma unroll
            for (int nt = 0; nt < 8; nt++) {
                const int p = nt >> 1, h = (nt & 1) * 2;
                mma16816(acc[mt][nt], AL[mt], BH[p][h], BH[p][h + 1]);
            }
    }
}

// 3-stage double-issued-ahead pipeline
__device__ __forceinline__ void gemm_pipeline(uint32_t smb, int nchunks,
                                              const __nv_bfloat16* Ah,
                                              const __nv_bfloat16* Al, int lda,
                                              const __nv_bfloat16* Bh,
                                              const __nv_bfloat16* Bl, int ldb,
                                              float acc[2][8][4], int tid,
                                              int lane, int wm, int wn) {
    load_chunk(smb, Ah, Al, lda, Bh, Bl, ldb, 0, tid);
    load_chunk(smb + STAGE_BYTES, Ah, Al, lda, Bh, Bl, ldb, 1, tid);
    int ld_stage = 2;   // stage index where chunk kc+2 goes
    int cp_stage = 0;   // stage index of chunk kc
    for (int kc = 0; kc < nchunks; kc++) {
        if (kc + 2 < nchunks) {
            load_chunk(smb + ld_stage * STAGE_BYTES, Ah, Al, lda, Bh, Bl, ldb,
                       kc + 2, tid);
            if (++ld_stage == NSTAGE) ld_stage = 0;
            cp_wait2();
        } else if (kc + 1 < nchunks) {
            cp_wait1();
        } else {
            cp_wait0();
        }
        __syncthreads();
        compute_chunk(smb + cp_stage * STAGE_BYTES, acc, lane, wm, wn);
        if (++cp_stage == NSTAGE) cp_stage = 0;
        __syncthreads();
    }
}

// ---------------------------------------------------------------------------
// Epilogues
// ---------------------------------------------------------------------------
__device__ __forceinline__ void store_acc_f32(float acc[2][8][4], float* dst,
                                              int ld, int m0, int n0, int mode,
                                              int lane, int wm, int wn) {
    #pragma unroll
    for (int mt = 0; mt < 2; mt++)
        #pragma unroll
        for (int nt = 0; nt < 8; nt++) {
            const int row = m0 + wm * 32 + mt * 16 + (lane >> 2);
            const int col = n0 + wn * 64 + nt * 8 + (lane & 3) * 2;
            float2 v0 = {acc[mt][nt][0], acc[mt][nt][1]};
            float2 v1 = {acc[mt][nt][2], acc[mt][nt][3]};
            if (mode == 1) {
                v0.x = (col + 0 > row) ? -1e30f : v0.x * SCALE;
                v0.y = (col + 1 > row) ? -1e30f : v0.y * SCALE;
                v1.x = (col + 0 > row + 8) ? -1e30f : v1.x * SCALE;
                v1.y = (col + 1 > row + 8) ? -1e30f : v1.y * SCALE;
            }
            *(float2*)(dst + (size_t)row * ld + col) = v0;
            *(float2*)(dst + (size_t)(row + 8) * ld + col) = v1;
        }
}

__device__ __forceinline__ void store_acc_split(float acc[2][8][4],
                                                __nv_bfloat16* hi,
                                                __nv_bfloat16* lo, int ld,
                                                int m0, int n0, int lane,
                                                int wm, int wn) {
    #pragma unroll
    for (int mt = 0; mt < 2; mt++)
        #pragma unroll
        for (int nt = 0; nt < 8; nt++) {
            const int row = m0 + wm * 32 + mt * 16 + (lane >> 2);
            const int col = n0 + wn * 64 + nt * 8 + (lane & 3) * 2;
            #pragma unroll
            for (int hh = 0; hh < 2; hh++) {
                const float a = acc[mt][nt][hh * 2 + 0];
                const float b = acc[mt][nt][hh * 2 + 1];
                const int r = row + hh * 8;
                __nv_bfloat16 ha = __float2bfloat16(a);
                __nv_bfloat16 hb = __float2bfloat16(b);
                *(__nv_bfloat162*)(hi + (size_t)r * ld + col) =
                    __nv_bfloat162(ha, hb);
                *(__nv_bfloat162*)(lo + (size_t)r * ld + col) = __nv_bfloat162(
                    __float2bfloat16(a - __bfloat162float(ha)),
                    __float2bfloat16(b - __bfloat162float(hb)));
            }
        }
}

// ---------------------------------------------------------------------------
// Prep kernels
// ---------------------------------------------------------------------------
__global__ void prep_x(const float4* __restrict__ x) {
    const size_t i = (size_t)blockIdx.x * blockDim.x + threadIdx.x;
    float4 v = x[i];
    __nv_bfloat16 h0 = __float2bfloat16(v.x), h1 = __float2bfloat16(v.y);
    __nv_bfloat16 h2 = __float2bfloat16(v.z), h3 = __float2bfloat16(v.w);
    ((__nv_bfloat162*)g_Xh)[i * 2] = __nv_bfloat162(h0, h1);
    ((__nv_bfloat162*)g_Xh)[i * 2 + 1] = __nv_bfloat162(h2, h3);
    ((__nv_bfloat162*)g_Xl)[i * 2] =
        __nv_bfloat162(__float2bfloat16(v.x - __bfloat162float(h0)),
                       __float2bfloat16(v.y - __bfloat162float(h1)));
    ((__nv_bfloat162*)g_Xl)[i * 2 + 1] =
        __nv_bfloat162(__float2bfloat16(v.z - __bfloat162float(h2)),
                       __float2bfloat16(v.w - __bfloat162float(h3)));
}

__global__ void prep_w(const float* __restrict__ Wq, const float* __restrict__ Wk,
                       const float* __restrict__ Wv) {
    __shared__ float t[32][33];
    const int w = blockIdx.z;
    const float* W = (w == 0) ? Wq : (w == 1) ? Wk : Wv;
    __nv_bfloat16* oh = g_WT_hi + (size_t)w * DIM * DIM;
    __nv_bfloat16* ol = g_WT_lo + (size_t)w * DIM * DIM;
    const int tx = threadIdx.x, ty = threadIdx.y;
    const int n0 = blockIdx.x * 32, k0 = blockIdx.y * 32;
    #pragma unroll
    for (int i = 0; i < 4; i++)
        t[ty + 8 * i][tx] = W[(size_t)(k0 + ty + 8 * i) * DIM + n0 + tx];
    __syncthreads();
    #pragma unroll
    for (int i = 0; i < 4; i++) {
        float v = t[tx][ty + 8 * i];
        __nv_bfloat16 h = __float2bfloat16(v);
        oh[(size_t)(n0 + ty + 8 * i) * DIM + k0 + tx] = h;
        ol[(size_t)(n0 + ty + 8 * i) * DIM + k0 + tx] =
            __float2bfloat16(v - __bfloat162float(h));
    }
}

__global__ void prep_vT() {
    __shared__ float t[32][33];
    const int b = blockIdx.z;
    const float* V = g_V + (size_t)b * SEQ * DIM;
    __nv_bfloat16* oh = g_VT_hi + (size_t)b * DIM * SEQ;
    __nv_bfloat16* ol = g_VT_lo + (size_t)b * DIM * SEQ;
    const int tx = threadIdx.x, ty = threadIdx.y;
    const int d0 = blockIdx.x * 32, s0 = blockIdx.y * 32;
    #pragma unroll
    for (int i = 0; i < 4; i++)
        t[ty + 8 * i][tx] = V[(size_t)(s0 + ty + 8 * i) * DIM + d0 + tx];
    __syncthreads();
    #pragma unroll
    for (int i = 0; i < 4; i++) {
        float v = t[tx][ty + 8 * i];
        __nv_bfloat16 h = __float2bfloat16(v);
        oh[(size_t)(d0 + ty + 8 * i) * SEQ + s0 + tx] = h;
        ol[(size_t)(d0 + ty + 8 * i) * SEQ + s0 + tx] =
            __float2bfloat16(v - __bfloat162float(h));
    }
}

// ---------------------------------------------------------------------------
// GEMM 1: QKV projection
// ---------------------------------------------------------------------------
__global__ void __launch_bounds__(256, 2) qkv_hmma() {
    extern __shared__ uint8_t dsm[];
    const uint32_t smb = su32(dsm);
    const int tid = threadIdx.x;
    const int lane = tid & 31;
    const int wid = tid >> 5;
    const int wm = wid & 3, wn = wid >> 2;

    const int w = blockIdx.z;
    const int m0 = blockIdx.y * 128;
    const int n0 = blockIdx.x * 128;
    const __nv_bfloat16* Ah = g_Xh + (size_t)m0 * DIM;
    const __nv_bfloat16* Al = g_Xl + (size_t)m0 * DIM;
    const __nv_bfloat16* Bh = g_WT_hi + (size_t)w * DIM * DIM + (size_t)n0 * DIM;
    const __nv_bfloat16* Bl = g_WT_lo + (size_t)w * DIM * DIM + (size_t)n0 * DIM;

    float acc[2][8][4] = {};
    gemm_pipeline(smb, DIM / 32, Ah, Al, DIM, Bh, Bl, DIM, acc, tid, lane, wm, wn);

    if (w == 2) {
        store_acc_f32(acc, g_V, DIM, m0, n0, 0, lane, wm, wn);
    } else if (w == 0) {
        store_acc_split(acc, g_Qh, g_Ql, DIM, m0, n0, lane, wm, wn);
    } else {
        store_acc_split(acc, g_Kh, g_Kl, DIM, m0, n0, lane, wm, wn);
    }
}

// ---------------------------------------------------------------------------
// GEMM 2: scores = scale * Q @ K^T, causal mask fused
// ---------------------------------------------------------------------------
__global__ void __launch_bounds__(256, 2) scores_hmma() {
    const int kt = blockIdx.x;
    const int qt = blockIdx.y;
    if (kt > qt) return;
    extern __shared__ uint8_t dsm[];
    const uint32_t smb = su32(dsm);
    const int tid = threadIdx.x;
    const int lane = tid & 31;
    const int wid = tid >> 5;
    const int wm = wid & 3, wn = wid >> 2;

    const int b = blockIdx.z;
    const int m0 = qt * 128;
    const int n0 = kt * 128;
    const __nv_bfloat16* Ah = g_Qh + (size_t)(b * SEQ + m0) * DIM;
    const __nv_bfloat16* Al = g_Ql + (size_t)(b * SEQ + m0) * DIM;
    const __nv_bfloat16* Bh = g_Kh + (size_t)(b * SEQ + n0) * DIM;
    const __nv_bfloat16* Bl = g_Kl + (size_t)(b * SEQ + n0) * DIM;

    float acc[2][8][4] = {};
    gemm_pipeline(smb, DIM / 32, Ah, Al, DIM, Bh, Bl, DIM, acc, tid, lane, wm, wn);

    store_acc_f32(acc, g_S + (size_t)b * SEQ * SEQ, SEQ, m0, n0, 1, lane, wm, wn);
}

// ---------------------------------------------------------------------------
// Kernel 3: row softmax, writes P as split bf16
// ---------------------------------------------------------------------------
__global__ void __launch_bounds__(256) softmax_rows() {
    const int q = blockIdx.x;
    const int b = blockIdx.y;
    const size_t base = (size_t)b * SEQ * SEQ + (size_t)q * SEQ;
    const float* row = g_S + base;
    const int L = ((q >> 7) + 1) << 7;

    const int tid = threadIdx.x;
    __shared__ float red[256];

    float vals[8];
    int cnt = 0;
    float m = -1e30f;
    for (int idx = tid; idx < L; idx += 256) {
        vals[cnt] = row[idx];
        m = fmaxf(m, vals[cnt]);
        cnt++;
    }
    red[tid] = m;
    __syncthreads();
    #pragma unroll
    for (int s = 128; s > 0; s >>= 1) {
        if (tid < s) red[tid] = fmaxf(red[tid], red[tid + s]);
        __syncthreads();
    }
    const float M = red[0];
    __syncthreads();

    float sum = 0.f;
    for (int i = 0; i < cnt; i++) {
        vals[i] = __expf(vals[i] - M);
        sum += vals[i];
    }
    red[tid] = sum;
    __syncthreads();
    #pragma unroll
    for (int s = 128; s > 0; s >>= 1) {
        if (tid < s) red[tid] += red[tid + s];
        __syncthreads();
    }
    const float inv = 1.0f / red[0];

    cnt = 0;
    for (int idx = tid; idx < L; idx += 256) {
        const float p = vals[cnt++] * inv;
        __nv_bfloat16 h = __float2bfloat16(p);
        g_Ph[base + idx] = h;
        g_Pl[base + idx] = __float2bfloat16(p - __bfloat162float(h));
    }
}

// ---------------------------------------------------------------------------
// GEMM 4: O = P @ V, causal K-extent
// ---------------------------------------------------------------------------
__global__ void __launch_bounds__(256, 2) pv_hmma(float* __restrict__ out) {
    extern __shared__ uint8_t dsm[];
    const uint32_t smb = su32(dsm);
    const int tid = threadIdx.x;
    const int lane = tid & 31;
    const int wid = tid >> 5;
    const int wm = wid & 3, wn = wid >> 2;

    const int et = blockIdx.x;
    const int qt = blockIdx.y;
    const int b  = blockIdx.z;
    const int m0 = qt * 128;
    const int n0 = et * 128;
    const int nchunks = (qt + 1) * 4;

    const __nv_bfloat16* Ah = g_Ph + (size_t)b * SEQ * SEQ + (size_t)m0 * SEQ;
    const __nv_bfloat16* Al = g_Pl + (size_t)b * SEQ * SEQ + (size_t)m0 * SEQ;
    const __nv_bfloat16* Bh = g_VT_hi + (size_t)b * DIM * SEQ + (size_t)n0 * SEQ;
    const __nv_bfloat16* Bl = g_VT_lo + (size_t)b * DIM * SEQ + (size_t)n0 * SEQ;

    float acc[2][8][4] = {};
    gemm_pipeline(smb, nchunks, Ah, Al, SEQ, Bh, Bl, SEQ, acc, tid, lane, wm, wn);

    store_acc_f32(acc, out + (size_t)b * SEQ * DIM, DIM, m0, n0, 0, lane, wm, wn);
}

// ---------------------------------------------------------------------------
extern "C" void kernel_launch(void* const* d_in, const int* in_sizes, int n_in,
                              void* d_out, int out_size) {
    const float* x  = (const float*)d_in[0];
    const float* Wq = (const float*)d_in[1];
    const float* Wk = (const float*)d_in[2];
    const float* Wv = (const float*)d_in[3];
    float* out = (float*)d_out;

    const int DSM = NSTAGE * STAGE_BYTES;  // 96KB
    static bool attr_done = false;
    if (!attr_done) {
        cudaFuncSetAttribute(qkv_hmma, cudaFuncAttributeMaxDynamicSharedMemorySize, DSM);
        cudaFuncSetAttribute(scores_hmma, cudaFuncAttributeMaxDynamicSharedMemorySize, DSM);
        cudaFuncSetAttribute(pv_hmma, cudaFuncAttributeMaxDynamicSharedMemorySize, DSM);
        attr_done = true;
    }

    prep_x<<<(MTOT * DIM / 4) / 256, 256>>>((const float4*)x);
    prep_w<<<dim3(DIM / 32, DIM / 32, 3), dim3(32, 8)>>>(Wq, Wk, Wv);
    qkv_hmma<<<dim3(DIM / 128, MTOT / 128, 3), 256, DSM>>>();
    prep_vT<<<dim3(DIM / 32, SEQ / 32, BATCH), dim3(32, 8)>>>();
    scores_hmma<<<dim3(SEQ / 128, SEQ / 128, BATCH), 256, DSM>>>();
    softmax_rows<<<dim3(SEQ, BATCH), 256>>>();
    pv_hmma<<<dim3(DIM / 128, SEQ / 128, BATCH), 256, DSM>>>(out);
}

// round 7
// speedup vs baseline: 1.0997x; 1.0997x over previous
#include <cuda_runtime.h>
#include <cuda_bf16.h>
#include <stdint.h>
#include <math.h>

#define BATCH 4
#define SEQ   2048
#define DIM   1024
#define MTOT  (BATCH * SEQ)   // 8192
#define SCALE 0.03125f        // 1/sqrt(1024)

// ---------------------------------------------------------------------------
// Device-global scratch (allocation-guard safe)
// ---------------------------------------------------------------------------
__device__ float g_V[(size_t)MTOT * DIM];                    // V fp32 (pre-transpose)
__device__ float g_S[(size_t)BATCH * SEQ * SEQ];             // raw scores
__device__ __nv_bfloat16 g_Xh[(size_t)MTOT * DIM];           // x split [m][k]
__device__ __nv_bfloat16 g_Xl[(size_t)MTOT * DIM];
__device__ __nv_bfloat16 g_Qh[(size_t)MTOT * DIM];           // Q split [m][d]
__device__ __nv_bfloat16 g_Ql[(size_t)MTOT * DIM];
__device__ __nv_bfloat16 g_Kh[(size_t)MTOT * DIM];           // K split [m][d]
__device__ __nv_bfloat16 g_Kl[(size_t)MTOT * DIM];
__device__ __nv_bfloat16 g_Ph[(size_t)BATCH * SEQ * SEQ];    // softmax P split [q][s]
__device__ __nv_bfloat16 g_Pl[(size_t)BATCH * SEQ * SEQ];
__device__ __nv_bfloat16 g_WT_hi[(size_t)3 * DIM * DIM];     // W^T split [w][n][k]
__device__ __nv_bfloat16 g_WT_lo[(size_t)3 * DIM * DIM];
__device__ __nv_bfloat16 g_VT_hi[(size_t)BATCH * DIM * SEQ]; // V^T split [b][d][s]
__device__ __nv_bfloat16 g_VT_lo[(size_t)BATCH * DIM * SEQ];

#define SWZ(o) ((o) ^ (((o) >> 3) & 0x70))
#define STAGE_BYTES 65536
// stage layout: ahi @0, alo @16384, bhi @32768, blo @49152

__device__ __forceinline__ uint32_t su32(const void* p) {
    uint32_t a;
    asm("{ .reg .u64 t; cvta.to.shared.u64 t, %1; cvt.u32.u64 %0, t; }"
        : "=r"(a) : "l"(p));
    return a;
}

__device__ __forceinline__ void ldsm4(uint32_t* r, uint32_t addr) {
    asm volatile("ldmatrix.sync.aligned.m8n8.x4.shared.b16 {%0,%1,%2,%3}, [%4];"
                 : "=r"(r[0]), "=r"(r[1]), "=r"(r[2]), "=r"(r[3]) : "r"(addr));
}

__device__ __forceinline__ void mma16816(float* d, const uint32_t* a,
                                         uint32_t b0, uint32_t b1) {
    asm volatile(
        "mma.sync.aligned.m16n8k16.row.col.f32.bf16.bf16.f32 "
        "{%0,%1,%2,%3}, {%4,%5,%6,%7}, {%8,%9}, {%0,%1,%2,%3};"
        : "+f"(d[0]), "+f"(d[1]), "+f"(d[2]), "+f"(d[3])
        : "r"(a[0]), "r"(a[1]), "r"(a[2]), "r"(a[3]), "r"(b0), "r"(b1));
}

__device__ __forceinline__ void cp_commit() {
    asm volatile("cp.async.commit_group;" ::: "memory");
}
__device__ __forceinline__ void cp_wait1() {
    asm volatile("cp.async.wait_group 1;" ::: "memory");
}
__device__ __forceinline__ void cp_wait0() {
    asm volatile("cp.async.wait_group 0;" ::: "memory");
}

// Async load of one 128x64 bf16 tile (K-major, SW128) into SMEM
__device__ __forceinline__ void async_tile(uint32_t dst, const __nv_bfloat16* src,
                                           int ld, int tid) {
    #pragma unroll
    for (int t = 0; t < 4; t++) {
        const int idx = tid + t * 256;
        const int row = idx >> 3;
        const int c = idx & 7;
        const uint32_t d = dst + SWZ((uint32_t)(row * 128 + c * 16));
        asm volatile("cp.async.cg.shared.global [%0], [%1], 16;"
                     :: "r"(d), "l"(src + (size_t)row * ld + c * 8));
    }
}

__device__ __forceinline__ void load_chunk(uint32_t stage_base,
                                           const __nv_bfloat16* Ah,
                                           const __nv_bfloat16* Al, int lda,
                                           const __nv_bfloat16* Bh,
                                           const __nv_bfloat16* Bl, int ldb,
                                           int kc, int tid) {
    async_tile(stage_base,         Ah + kc * 64, lda, tid);
    async_tile(stage_base + 16384, Al + kc * 64, lda, tid);
    async_tile(stage_base + 32768, Bh + kc * 64, ldb, tid);
    async_tile(stage_base + 49152, Bl + kc * 64, ldb, tid);
    cp_commit();
}

// ---------------------------------------------------------------------------
// Fragment loads for one k16 step (12 x ldmatrix.x4)
// ---------------------------------------------------------------------------
__device__ __forceinline__ void ld_frags(uint32_t ahi_b, uint32_t alo_b,
                                         uint32_t bhi_b, uint32_t blo_b, int ks,
                                         int ar, int ac, int br, int bc,
                                         int wm, int wn,
                                         uint32_t AH[2][4], uint32_t AL[2][4],
                                         uint32_t BH[4][4], uint32_t BL[4][4]) {
    #pragma unroll
    for (int mt = 0; mt < 2; mt++) {
        const uint32_t off =
            SWZ((uint32_t)((wm * 32 + mt * 16 + ar) * 128 + ks * 32 + ac));
        ldsm4(AH[mt], ahi_b + off);
        ldsm4(AL[mt], alo_b + off);
    }
    #pragma unroll
    for (int p = 0; p < 4; p++) {
        const uint32_t off =
            SWZ((uint32_t)((wn * 64 + p * 16 + br) * 128 + ks * 32 + bc));
        ldsm4(BH[p], bhi_b + off);
        ldsm4(BL[p], blo_b + off);
    }
}

// ---------------------------------------------------------------------------
// Warp-level K-chunk compute: 4 k16 steps, bf16x3, term-major MMA order,
// register double-buffered fragments (prefetch ks+1 before MMAs of ks)
// ---------------------------------------------------------------------------
__device__ __forceinline__ void compute_chunk(uint32_t stage_base,
                                              float acc[2][8][4], int lane,
                                              int wm, int wn) {
    const uint32_t ahi_b = stage_base;
    const uint32_t alo_b = stage_base + 16384;
    const uint32_t bhi_b = stage_base + 32768;
    const uint32_t blo_b = stage_base + 49152;
    const int ar = lane & 15;
    const int ac = (lane >> 4) * 16;
    const int br = ((lane >> 4) & 1) * 8 + (lane & 7);
    const int bc = ((lane >> 3) & 1) * 16;

    uint32_t AH[2][2][4], AL[2][2][4], BH[2][4][4], BL[2][4][4];
    ld_frags(ahi_b, alo_b, bhi_b, blo_b, 0, ar, ac, br, bc, wm, wn,
             AH[0], AL[0], BH[0], BL[0]);
    #pragma unroll
    for (int ks = 0; ks < 4; ks++) {
        const int cur = ks & 1, nxt = cur ^ 1;
        if (ks < 3)
            ld_frags(ahi_b, alo_b, bhi_b, blo_b, ks + 1, ar, ac, br, bc, wm, wn,
                     AH[nxt], AL[nxt], BH[nxt], BL[nxt]);
        // term-major: consecutive MMAs always hit different accumulators
        #pragma unroll
        for (int mt = 0; mt < 2; mt++)
            #pragma unroll
            for (int nt = 0; nt < 8; nt++) {
                const int p = nt >> 1, h = (nt & 1) * 2;
                mma16816(acc[mt][nt], AH[cur][mt], BH[cur][p][h], BH[cur][p][h + 1]);
            }
        #pragma unroll
        for (int mt = 0; mt < 2; mt++)
            #pragma unroll
            for (int nt = 0; nt < 8; nt++) {
                const int p = nt >> 1, h = (nt & 1) * 2;
                mma16816(acc[mt][nt], AH[cur][mt], BL[cur][p][h], BL[cur][p][h + 1]);
            }
        #pragma unroll
        for (int mt = 0; mt < 2; mt++)
            #pragma unroll
            for (int nt = 0; nt < 8; nt++) {
                const int p = nt >> 1, h = (nt & 1) * 2;
                mma16816(acc[mt][nt], AL[cur][mt], BH[cur][p][h], BH[cur][p][h + 1]);
            }
    }
}

// 2-stage double-buffered pipeline (Round-5 structure)
__device__ __forceinline__ void gemm_pipeline(uint32_t smb, int nchunks,
                                              const __nv_bfloat16* Ah,
                                              const __nv_bfloat16* Al, int lda,
                                              const __nv_bfloat16* Bh,
                                              const __nv_bfloat16* Bl, int ldb,
                                              float acc[2][8][4], int tid,
                                              int lane, int wm, int wn) {
    load_chunk(smb, Ah, Al, lda, Bh, Bl, ldb, 0, tid);
    for (int kc = 0; kc < nchunks; kc++) {
        if (kc + 1 < nchunks) {
            load_chunk(smb + ((kc + 1) & 1) * STAGE_BYTES, Ah, Al, lda, Bh, Bl,
                       ldb, kc + 1, tid);
            cp_wait1();
        } else {
            cp_wait0();
        }
        __syncthreads();
        compute_chunk(smb + (kc & 1) * STAGE_BYTES, acc, lane, wm, wn);
        __syncthreads();
    }
}

// ---------------------------------------------------------------------------
// Epilogues
// ---------------------------------------------------------------------------
__device__ __forceinline__ void store_acc_f32(float acc[2][8][4], float* dst,
                                              int ld, int m0, int n0, int mode,
                                              int lane, int wm, int wn) {
    #pragma unroll
    for (int mt = 0; mt < 2; mt++)
        #pragma unroll
        for (int nt = 0; nt < 8; nt++) {
            const int row = m0 + wm * 32 + mt * 16 + (lane >> 2);
            const int col = n0 + wn * 64 + nt * 8 + (lane & 3) * 2;
            float2 v0 = {acc[mt][nt][0], acc[mt][nt][1]};
            float2 v1 = {acc[mt][nt][2], acc[mt][nt][3]};
            if (mode == 1) {
                v0.x = (col + 0 > row) ? -1e30f : v0.x * SCALE;
                v0.y = (col + 1 > row) ? -1e30f : v0.y * SCALE;
                v1.x = (col + 0 > row + 8) ? -1e30f : v1.x * SCALE;
                v1.y = (col + 1 > row + 8) ? -1e30f : v1.y * SCALE;
            }
            *(float2*)(dst + (size_t)row * ld + col) = v0;
            *(float2*)(dst + (size_t)(row + 8) * ld + col) = v1;
        }
}

__device__ __forceinline__ void store_acc_split(float acc[2][8][4],
                                                __nv_bfloat16* hi,
                                                __nv_bfloat16* lo, int ld,
                                                int m0, int n0, int lane,
                                                int wm, int wn) {
    #pragma unroll
    for (int mt = 0; mt < 2; mt++)
        #pragma unroll
        for (int nt = 0; nt < 8; nt++) {
            const int row = m0 + wm * 32 + mt * 16 + (lane >> 2);
            const int col = n0 + wn * 64 + nt * 8 + (lane & 3) * 2;
            #pragma unroll
            for (int hh = 0; hh < 2; hh++) {
                const float a = acc[mt][nt][hh * 2 + 0];
                const float b = acc[mt][nt][hh * 2 + 1];
                const int r = row + hh * 8;
                __nv_bfloat16 ha = __float2bfloat16(a);
                __nv_bfloat16 hb = __float2bfloat16(b);
                *(__nv_bfloat162*)(hi + (size_t)r * ld + col) =
                    __nv_bfloat162(ha, hb);
                *(__nv_bfloat162*)(lo + (size_t)r * ld + col) = __nv_bfloat162(
                    __float2bfloat16(a - __bfloat162float(ha)),
                    __float2bfloat16(b - __bfloat162float(hb)));
            }
        }
}

// ---------------------------------------------------------------------------
// Prep kernels
// ---------------------------------------------------------------------------
__global__ void prep_x(const float4* __restrict__ x) {
    const size_t i = (size_t)blockIdx.x * blockDim.x + threadIdx.x;
    float4 v = x[i];
    __nv_bfloat16 h0 = __float2bfloat16(v.x), h1 = __float2bfloat16(v.y);
    __nv_bfloat16 h2 = __float2bfloat16(v.z), h3 = __float2bfloat16(v.w);
    ((__nv_bfloat162*)g_Xh)[i * 2] = __nv_bfloat162(h0, h1);
    ((__nv_bfloat162*)g_Xh)[i * 2 + 1] = __nv_bfloat162(h2, h3);
    ((__nv_bfloat162*)g_Xl)[i * 2] =
        __nv_bfloat162(__float2bfloat16(v.x - __bfloat162float(h0)),
                       __float2bfloat16(v.y - __bfloat162float(h1)));
    ((__nv_bfloat162*)g_Xl)[i * 2 + 1] =
        __nv_bfloat162(__float2bfloat16(v.z - __bfloat162float(h2)),
                       __float2bfloat16(v.w - __bfloat162float(h3)));
}

__global__ void prep_w(const float* __restrict__ Wq, const float* __restrict__ Wk,
                       const float* __restrict__ Wv) {
    __shared__ float t[32][33];
    const int w = blockIdx.z;
    const float* W = (w == 0) ? Wq : (w == 1) ? Wk : Wv;
    __nv_bfloat16* oh = g_WT_hi + (size_t)w * DIM * DIM;
    __nv_bfloat16* ol = g_WT_lo + (size_t)w * DIM * DIM;
    const int tx = threadIdx.x, ty = threadIdx.y;
    const int n0 = blockIdx.x * 32, k0 = blockIdx.y * 32;
    #pragma unroll
    for (int i = 0; i < 4; i++)
        t[ty + 8 * i][tx] = W[(size_t)(k0 + ty + 8 * i) * DIM + n0 + tx];
    __syncthreads();
    #pragma unroll
    for (int i = 0; i < 4; i++) {
        float v = t[tx][ty + 8 * i];
        __nv_bfloat16 h = __float2bfloat16(v);
        oh[(size_t)(n0 + ty + 8 * i) * DIM + k0 + tx] = h;
        ol[(size_t)(n0 + ty + 8 * i) * DIM + k0 + tx] =
            __float2bfloat16(v - __bfloat162float(h));
    }
}

__global__ void prep_vT() {
    __shared__ float t[32][33];
    const int b = blockIdx.z;
    const float* V = g_V + (size_t)b * SEQ * DIM;
    __nv_bfloat16* oh = g_VT_hi + (size_t)b * DIM * SEQ;
    __nv_bfloat16* ol = g_VT_lo + (size_t)b * DIM * SEQ;
    const int tx = threadIdx.x, ty = threadIdx.y;
    const int d0 = blockIdx.x * 32, s0 = blockIdx.y * 32;
    #pragma unroll
    for (int i = 0; i < 4; i++)
        t[ty + 8 * i][tx] = V[(size_t)(s0 + ty + 8 * i) * DIM + d0 + tx];
    __syncthreads();
    #pragma unroll
    for (int i = 0; i < 4; i++) {
        float v = t[tx][ty + 8 * i];
        __nv_bfloat16 h = __float2bfloat16(v);
        oh[(size_t)(d0 + ty + 8 * i) * SEQ + s0 + tx] = h;
        ol[(size_t)(d0 + ty + 8 * i) * SEQ + s0 + tx] =
            __float2bfloat16(v - __bfloat162float(h));
    }
}

// ---------------------------------------------------------------------------
// GEMM 1: QKV projection
// ---------------------------------------------------------------------------
__global__ void __launch_bounds__(256) qkv_hmma() {
    extern __shared__ uint8_t dsm[];
    const uint32_t smb = su32(dsm);
    const int tid = threadIdx.x;
    const int lane = tid & 31;
    const int wid = tid >> 5;
    const int wm = wid & 3, wn = wid >> 2;

    const int w = blockIdx.z;
    const int m0 = blockIdx.y * 128;
    const int n0 = blockIdx.x * 128;
    const __nv_bfloat16* Ah = g_Xh + (size_t)m0 * DIM;
    const __nv_bfloat16* Al = g_Xl + (size_t)m0 * DIM;
    const __nv_bfloat16* Bh = g_WT_hi + (size_t)w * DIM * DIM + (size_t)n0 * DIM;
    const __nv_bfloat16* Bl = g_WT_lo + (size_t)w * DIM * DIM + (size_t)n0 * DIM;

    float acc[2][8][4] = {};
    gemm_pipeline(smb, DIM / 64, Ah, Al, DIM, Bh, Bl, DIM, acc, tid, lane, wm, wn);

    if (w == 2) {
        store_acc_f32(acc, g_V, DIM, m0, n0, 0, lane, wm, wn);
    } else if (w == 0) {
        store_acc_split(acc, g_Qh, g_Ql, DIM, m0, n0, lane, wm, wn);
    } else {
        store_acc_split(acc, g_Kh, g_Kl, DIM, m0, n0, lane, wm, wn);
    }
}

// ---------------------------------------------------------------------------
// GEMM 2: scores = scale * Q @ K^T, causal mask fused
// ---------------------------------------------------------------------------
__global__ void __launch_bounds__(256) scores_hmma() {
    const int kt = blockIdx.x;
    const int qt = blockIdx.y;
    if (kt > qt) return;
    extern __shared__ uint8_t dsm[];
    const uint32_t smb = su32(dsm);
    const int tid = threadIdx.x;
    const int lane = tid & 31;
    const int wid = tid >> 5;
    const int wm = wid & 3, wn = wid >> 2;

    const int b = blockIdx.z;
    const int m0 = qt * 128;
    const int n0 = kt * 128;
    const __nv_bfloat16* Ah = g_Qh + (size_t)(b * SEQ + m0) * DIM;
    const __nv_bfloat16* Al = g_Ql + (size_t)(b * SEQ + m0) * DIM;
    const __nv_bfloat16* Bh = g_Kh + (size_t)(b * SEQ + n0) * DIM;
    const __nv_bfloat16* Bl = g_Kl + (size_t)(b * SEQ + n0) * DIM;

    float acc[2][8][4] = {};
    gemm_pipeline(smb, DIM / 64, Ah, Al, DIM, Bh, Bl, DIM, acc, tid, lane, wm, wn);

    store_acc_f32(acc, g_S + (size_t)b * SEQ * SEQ, SEQ, m0, n0, 1, lane, wm, wn);
}

// ---------------------------------------------------------------------------
// Kernel 3: row softmax, writes P as split bf16
// ---------------------------------------------------------------------------
__global__ void __launch_bounds__(256) softmax_rows() {
    const int q = blockIdx.x;
    const int b = blockIdx.y;
    const size_t base = (size_t)b * SEQ * SEQ + (size_t)q * SEQ;
    const float* row = g_S + base;
    const int L = ((q >> 7) + 1) << 7;

    const int tid = threadIdx.x;
    __shared__ float red[256];

    float vals[8];
    int cnt = 0;
    float m = -1e30f;
    for (int idx = tid; idx < L; idx += 256) {
        vals[cnt] = row[idx];
        m = fmaxf(m, vals[cnt]);
        cnt++;
    }
    red[tid] = m;
    __syncthreads();
    #pragma unroll
    for (int s = 128; s > 0; s >>= 1) {
        if (tid < s) red[tid] = fmaxf(red[tid], red[tid + s]);
        __syncthreads();
    }
    const float M = red[0];
    __syncthreads();

    float sum = 0.f;
    for (int i = 0; i < cnt; i++) {
        vals[i] = __expf(vals[i] - M);
        sum += vals[i];
    }
    red[tid] = sum;
    __syncthreads();
    #pragma unroll
    for (int s = 128; s > 0; s >>= 1) {
        if (tid < s) red[tid] += red[tid + s];
        __syncthreads();
    }
    const float inv = 1.0f / red[0];

    cnt = 0;
    for (int idx = tid; idx < L; idx += 256) {
        const float p = vals[cnt++] * inv;
        __nv_bfloat16 h = __float2bfloat16(p);
        g_Ph[base + idx] = h;
        g_Pl[base + idx] = __float2bfloat16(p - __bfloat162float(h));
    }
}

// ---------------------------------------------------------------------------
// GEMM 4: O = P @ V, causal K-extent, heaviest q-tiles scheduled first
// ---------------------------------------------------------------------------
__global__ void __launch_bounds__(256) pv_hmma(float* __restrict__ out) {
    extern __shared__ uint8_t dsm[];
    const uint32_t smb = su32(dsm);
    const int tid = threadIdx.x;
    const int lane = tid & 31;
    const int wid = tid >> 5;
    const int wm = wid & 3, wn = wid >> 2;

    const int et = blockIdx.x;
    const int qt = (SEQ / 128 - 1) - blockIdx.y;   // heavy tiles first
    const int b  = blockIdx.z;
    const int m0 = qt * 128;
    const int n0 = et * 128;
    const int nchunks = (qt + 1) * 2;

    const __nv_bfloat16* Ah = g_Ph + (size_t)b * SEQ * SEQ + (size_t)m0 * SEQ;
    const __nv_bfloat16* Al = g_Pl + (size_t)b * SEQ * SEQ + (size_t)m0 * SEQ;
    const __nv_bfloat16* Bh = g_VT_hi + (size_t)b * DIM * SEQ + (size_t)n0 * SEQ;
    const __nv_bfloat16* Bl = g_VT_lo + (size_t)b * DIM * SEQ + (size_t)n0 * SEQ;

    float acc[2][8][4] = {};
    gemm_pipeline(smb, nchunks, Ah, Al, SEQ, Bh, Bl, SEQ, acc, tid, lane, wm, wn);

    store_acc_f32(acc, out + (size_t)b * SEQ * DIM, DIM, m0, n0, 0, lane, wm, wn);
}

// ---------------------------------------------------------------------------
extern "C" void kernel_launch(void* const* d_in, const int* in_sizes, int n_in,
                              void* d_out, int out_size) {
    const float* x  = (const float*)d_in[0];
    const float* Wq = (const float*)d_in[1];
    const float* Wk = (const float*)d_in[2];
    const float* Wv = (const float*)d_in[3];
    float* out = (float*)d_out;

    const int DSM = 2 * STAGE_BYTES;  // 128KB
    static bool attr_done = false;
    if (!attr_done) {
        cudaFuncSetAttribute(qkv_hmma, cudaFuncAttributeMaxDynamicSharedMemorySize, DSM);
        cudaFuncSetAttribute(scores_hmma, cudaFuncAttributeMaxDynamicSharedMemorySize, DSM);
        cudaFuncSetAttribute(pv_hmma, cudaFuncAttributeMaxDynamicSharedMemorySize, DSM);
        attr_done = true;
    }

    prep_x<<<(MTOT * DIM / 4) / 256, 256>>>((const float4*)x);
    prep_w<<<dim3(DIM / 32, DIM / 32, 3), dim3(32, 8)>>>(Wq, Wk, Wv);
    qkv_hmma<<<dim3(DIM / 128, MTOT / 128, 3), 256, DSM>>>();
    prep_vT<<<dim3(DIM / 32, SEQ / 32, BATCH), dim3(32, 8)>>>();
    scores_hmma<<<dim3(SEQ / 128, SEQ / 128, BATCH), 256, DSM>>>();
    softmax_rows<<<dim3(SEQ, BATCH), 256>>>();
    pv_hmma<<<dim3(DIM / 128, SEQ / 128, BATCH), 256, DSM>>>(out);
}